// round 3
// baseline (speedup 1.0000x reference)
#include <cuda_runtime.h>

#define HW 225
#define ST 226           // 225 positions + 1 guaranteed-zero slot per channel
#define NCH 128
#define TAPSTRIDE (128*128)
#define SMEM_BYTES (2*NCH*ST*4)

// per-direction tap offsets (OFFSETS in the reference):
// d0 horiz, d1 vert, d2 anti-diag, d3 main diag
__constant__ int c_DI0[4] = { 0,-1, 1,-1};
__constant__ int c_DJ0[4] = {-1, 0,-1,-1};
__constant__ int c_DI2[4] = { 0, 1,-1, 1};
__constant__ int c_DJ2[4] = { 1, 0, 1, 1};

// transposed res dconv weights: [i][t][o][c] (c contiguous for LDG.128)
__device__ __align__(16) float g_dwt[4*3*128*128];

__global__ void prep_kernel(const float* __restrict__ w) {
    const int n = 4*3*128*128;
    for (int idx = blockIdx.x*blockDim.x + threadIdx.x; idx < n;
         idx += gridDim.x*blockDim.x) {
        int c = idx & 127;
        int r = idx >> 7;
        int o = r & 127;
        r >>= 7;            // r = i*3 + t
        int t = r % 3;
        int i = r / 3;
        g_dwt[idx] = w[((i*128 + o)*128 + c)*3 + t];
    }
}

__device__ __forceinline__ float silu_f(float x) {
    return x * (1.0f / (1.0f + __expf(-x)));
}

// One fused layer over Cin=128: out[o][p] = (act?)(sum_t sum_c w[t][o][c]*in[c][p+dt]) + bias
// Optionally adds a residual (own element only) and/or writes to global.
template<int NTAPS, bool ACT, bool RESID, bool TOGLOBAL>
__device__ __forceinline__ void layer_c128(
    const float* __restrict__ sin,
    float* sout,                    // smem out (if !TOGLOBAL)
    float* gout,                    // global out base (if TOGLOBAL), rows of 225
    const float* __restrict__ w,    // [NTAPS][Co][128], c contiguous
    const float* __restrict__ bias,
    const float* resid,
    int di0, int dj0, int di2, int dj2)
{
    const int tid = threadIdx.x;
    const int oz    = TOGLOBAL ? (tid >> 5) : (tid >> 4);
    const int pl    = TOGLOBAL ? (tid & 31) : (tid & 15);
    const int lanes = TOGLOBAL ? 32 : 16;
    const int ob = oz * 8;

    float b8[8];
#pragma unroll
    for (int u = 0; u < 8; u++) b8[u] = bias[ob + u];

    const int d0 = di0*15 + dj0;
    const int d2 = di2*15 + dj2;
    const int nchunks = TOGLOBAL ? 2 : 4;

#pragma unroll 1
    for (int ch = 0; ch < nchunks; ch++) {
        int pv[4], pt0[4], pt2[4];
        bool wrv[4];
#pragma unroll
        for (int j = 0; j < 4; j++) {
            int p = pl + lanes*(ch*4 + j);
            bool v = p < HW;
            wrv[j] = v;
            pv[j] = v ? p : HW;        // invalid -> zero slot
            pt0[j] = HW; pt2[j] = HW;
            if (NTAPS == 3) {
                int pi = p / 15, pj = p - pi*15;
                if (v && (unsigned)(pi+di0) < 15u && (unsigned)(pj+dj0) < 15u)
                    pt0[j] = p + d0;
                if (v && (unsigned)(pi+di2) < 15u && (unsigned)(pj+dj2) < 15u)
                    pt2[j] = p + d2;
            }
        }

        float acc[8][4];
#pragma unroll
        for (int u = 0; u < 8; u++)
#pragma unroll
            for (int j = 0; j < 4; j++) acc[u][j] = 0.f;

#pragma unroll
        for (int t = 0; t < NTAPS; t++) {
            const float* wt = w + t*TAPSTRIDE;
            int pcur[4];
#pragma unroll
            for (int j = 0; j < 4; j++)
                pcur[j] = (NTAPS == 3)
                        ? (t == 0 ? pt0[j] : (t == 1 ? pv[j] : pt2[j]))
                        : pv[j];

#pragma unroll 2
            for (int c4 = 0; c4 < 32; c4++) {
                float4 w4[8];
#pragma unroll
                for (int u = 0; u < 8; u++)
                    w4[u] = *reinterpret_cast<const float4*>(wt + (ob+u)*128 + c4*4);
                float vv[4][4];
#pragma unroll
                for (int j = 0; j < 4; j++) {
#pragma unroll
                    for (int cc = 0; cc < 4; cc++)
                        vv[j][cc] = sin[(c4*4 + cc)*ST + pcur[j]];
                }
#pragma unroll
                for (int u = 0; u < 8; u++) {
#pragma unroll
                    for (int j = 0; j < 4; j++) {
                        acc[u][j] = fmaf(w4[u].x, vv[j][0], acc[u][j]);
                        acc[u][j] = fmaf(w4[u].y, vv[j][1], acc[u][j]);
                        acc[u][j] = fmaf(w4[u].z, vv[j][2], acc[u][j]);
                        acc[u][j] = fmaf(w4[u].w, vv[j][3], acc[u][j]);
                    }
                }
            }
        }

#pragma unroll
        for (int u = 0; u < 8; u++) {
#pragma unroll
            for (int j = 0; j < 4; j++) {
                float val = acc[u][j] + b8[u];
                if (ACT)   val = silu_f(val);
                if (RESID) val += resid[(ob+u)*ST + pv[j]];
                if (wrv[j]) {
                    if (TOGLOBAL) gout[(ob+u)*HW + pv[j]] = val;
                    else          sout[(ob+u)*ST + pv[j]] = val;
                }
            }
        }
    }
}

__global__ void __launch_bounds__(256, 1)
mix9s_kernel(const float* __restrict__ x,
             const float* __restrict__ dw0, const float* __restrict__ db0,
             const float* __restrict__ rdb,
             const float* __restrict__ rpw, const float* __restrict__ rpb,
             const float* __restrict__ cw1, const float* __restrict__ cb1,
             const float* __restrict__ cw2, const float* __restrict__ cb2,
             const float* __restrict__ fw,  const float* __restrict__ fb,
             float* __restrict__ out)
{
    extern __shared__ float smem[];
    float* bufA = smem;
    float* bufB = smem + NCH*ST;

    const int tid = threadIdx.x;
    const int b = blockIdx.x & 255;
    const int d = blockIdx.x >> 8;
    const int di0 = c_DI0[d], dj0 = c_DJ0[d], di2 = c_DI2[d], dj2 = c_DJ2[d];

    // init zero slots + stage x (2 channels) into bufB
    if (tid < NCH) { bufA[tid*ST + HW] = 0.f; bufB[tid*ST + HW] = 0.f; }
    const float* xb = x + b*(2*HW);
    for (int idx = tid; idx < 2*HW; idx += 256) {
        int c = idx / HW;
        int p = idx - c*HW;
        bufB[c*ST + p] = xb[idx];
    }
    __syncthreads();

    // ---- dconv0: Cin=2, 3 taps, silu -> bufA ----
    {
        const int oz = tid >> 4, pl = tid & 15;
        const int ob = oz * 8;
        float wr_[8][2][3];
#pragma unroll
        for (int u = 0; u < 8; u++)
#pragma unroll
            for (int c = 0; c < 2; c++)
#pragma unroll
                for (int t = 0; t < 3; t++)
                    wr_[u][c][t] = dw0[((ob+u)*2 + c)*3 + t];
        float b8[8];
#pragma unroll
        for (int u = 0; u < 8; u++) b8[u] = db0[ob+u];

        const int d0 = di0*15 + dj0;
        const int d2 = di2*15 + dj2;
#pragma unroll 1
        for (int ch = 0; ch < 4; ch++) {
            int pv[4], pt0[4], pt2[4];
            bool wrv[4];
#pragma unroll
            for (int j = 0; j < 4; j++) {
                int p = pl + 16*(ch*4 + j);
                bool v = p < HW;
                wrv[j] = v;
                pv[j] = v ? p : HW;
                pt0[j] = HW; pt2[j] = HW;
                int pi = p / 15, pj = p - pi*15;
                if (v && (unsigned)(pi+di0) < 15u && (unsigned)(pj+dj0) < 15u)
                    pt0[j] = p + d0;
                if (v && (unsigned)(pi+di2) < 15u && (unsigned)(pj+dj2) < 15u)
                    pt2[j] = p + d2;
            }
#pragma unroll
            for (int j = 0; j < 4; j++) {
                float v0[2], vc[2], v2[2];
#pragma unroll
                for (int c = 0; c < 2; c++) {
                    v0[c] = bufB[c*ST + pt0[j]];
                    vc[c] = bufB[c*ST + pv[j]];
                    v2[c] = bufB[c*ST + pt2[j]];
                }
#pragma unroll
                for (int u = 0; u < 8; u++) {
                    float a = b8[u];
#pragma unroll
                    for (int c = 0; c < 2; c++) {
                        a = fmaf(wr_[u][c][0], v0[c], a);
                        a = fmaf(wr_[u][c][1], vc[c], a);
                        a = fmaf(wr_[u][c][2], v2[c], a);
                    }
                    a = silu_f(a);
                    if (wrv[j]) bufA[(ob+u)*ST + pv[j]] = a;
                }
            }
        }
    }
    __syncthreads();

    // ---- 4 directional res blocks ----
#pragma unroll 1
    for (int i = 0; i < 4; i++) {
        layer_c128<3, true, false, false>(bufA, bufB, nullptr,
            g_dwt + i*3*TAPSTRIDE, rdb + i*128, nullptr, di0, dj0, di2, dj2);
        __syncthreads();
        layer_c128<1, true, true, false>(bufB, bufA, nullptr,
            rpw + i*TAPSTRIDE, rpb + i*128, bufA, 0, 0, 0, 0);
        __syncthreads();
    }

    // ---- Conv0d res block ----
    layer_c128<1, true, false, false>(bufA, bufB, nullptr, cw1, cb1, nullptr, 0,0,0,0);
    __syncthreads();
    layer_c128<1, true, true, false>(bufB, bufA, nullptr, cw2, cb2, bufA, 0,0,0,0);
    __syncthreads();

    // ---- final 1x1 (128 -> 64), no activation, straight to global ----
    layer_c128<1, false, false, true>(bufA, nullptr, out + (b*4 + d)*64*HW,
                                      fw, fb, nullptr, 0,0,0,0);
}

extern "C" void kernel_launch(void* const* d_in, const int* in_sizes, int n_in,
                              void* d_out, int out_size) {
    (void)in_sizes; (void)n_in; (void)out_size;
    const float* x   = (const float*)d_in[0];
    const float* dw0 = (const float*)d_in[1];
    const float* db0 = (const float*)d_in[2];
    const float* rdw = (const float*)d_in[3];
    const float* rdb = (const float*)d_in[4];
    const float* rpw = (const float*)d_in[5];
    const float* rpb = (const float*)d_in[6];
    const float* cw1 = (const float*)d_in[7];
    const float* cb1 = (const float*)d_in[8];
    const float* cw2 = (const float*)d_in[9];
    const float* cb2 = (const float*)d_in[10];
    const float* fw  = (const float*)d_in[11];
    const float* fb  = (const float*)d_in[12];
    float* out = (float*)d_out;

    cudaFuncSetAttribute(mix9s_kernel,
                         cudaFuncAttributeMaxDynamicSharedMemorySize, SMEM_BYTES);

    prep_kernel<<<768, 256>>>(rdw);
    mix9s_kernel<<<1024, 256, SMEM_BYTES>>>(
        x, dw0, db0, rdb, rpw, rpb, cw1, cb1, cw2, cb2, fw, fb, out);
}

// round 4
// speedup vs baseline: 1.0370x; 1.0370x over previous
#include <cuda_runtime.h>

#define HW 225
#define ZROW 225          // guaranteed-zero row (all 128 channels zero)
#define NROWS 226
#define NCH 128
#define TAPSTRIDE (128*128)
#define SMEM_FLOATS (2*NROWS*NCH)
#define SMEM_BYTES (SMEM_FLOATS*4)

// per-direction tap offsets: d0 horiz, d1 vert, d2 anti-diag, d3 main diag
__constant__ int c_DI0[4] = { 0,-1, 1,-1};
__constant__ int c_DJ0[4] = {-1, 0,-1,-1};
__constant__ int c_DI2[4] = { 0, 1,-1, 1};
__constant__ int c_DJ2[4] = { 1, 0, 1, 1};

// transposed res dconv weights: [i][t][o][c] (c contiguous for LDG.128)
__device__ __align__(16) float g_dwt[4*3*128*128];

__global__ void prep_kernel(const float* __restrict__ w) {
    const int n = 4*3*128*128;
    for (int idx = blockIdx.x*blockDim.x + threadIdx.x; idx < n;
         idx += gridDim.x*blockDim.x) {
        int c = idx & 127;
        int r = idx >> 7;
        int o = r & 127;
        r >>= 7;            // r = i*3 + t
        int t = r % 3;
        int i = r / 3;
        g_dwt[idx] = w[((i*128 + o)*128 + c)*3 + t];
    }
}

__device__ __forceinline__ float silu_f(float x) {
    return x * (1.0f / (1.0f + __expf(-x)));
}

// swizzled 16B-granule index for smem layout [row p][128 channels]
// granule (p, c4) -> p*32 + (c4 ^ (p&7));  conflict-free LDS.128/STS.128 for
// consecutive p within a quarter-warp.
__device__ __forceinline__ int gran(int p, int c4) {
    return p*32 + (c4 ^ (p & 7));
}

// One layer over Cin=128. Each thread: 4 outputs (ob..ob+3) x 4 positions/chunk.
// Smem is position-major swizzled. Residual add is element-owned (race-free).
template<int NTAPS, bool ACT, bool RESID, bool TOGLOBAL>
__device__ __forceinline__ void layer_c128(
    const float4* __restrict__ s4in,
    float4* s4out,                  // smem out (if !TOGLOBAL)
    float* gout,                    // global out base (if TOGLOBAL), rows of 225
    const float* __restrict__ w,    // [NTAPS][Co][128], c contiguous
    const float* __restrict__ bias,
    const float4* s4res,
    int di0, int dj0, int di2, int dj2)
{
    const int tid = threadIdx.x;
    const int oz    = TOGLOBAL ? (tid >> 5) : (tid >> 4);
    const int pl    = TOGLOBAL ? (tid & 31) : (tid & 15);
    const int lanes = TOGLOBAL ? 32 : 16;
    const int ob = oz * 4;
    const int obc4 = oz;            // ob>>2

    float b4[4];
#pragma unroll
    for (int u = 0; u < 4; u++) b4[u] = bias[ob + u];

    const int d0 = di0*15 + dj0;
    const int d2 = di2*15 + dj2;
    const int nchunks = TOGLOBAL ? 2 : 4;

#pragma unroll 1
    for (int ch = 0; ch < nchunks; ch++) {
        int rowv[4], row0[4], row2[4];
        bool wrv[4];
#pragma unroll
        for (int j = 0; j < 4; j++) {
            int p = pl + lanes*(ch*4 + j);
            bool v = p < HW;
            wrv[j] = v;
            rowv[j] = v ? p : ZROW;
            row0[j] = ZROW; row2[j] = ZROW;
            if (NTAPS == 3) {
                int pi = p / 15, pj = p - pi*15;
                if (v && (unsigned)(pi+di0) < 15u && (unsigned)(pj+dj0) < 15u)
                    row0[j] = p + d0;
                if (v && (unsigned)(pi+di2) < 15u && (unsigned)(pj+dj2) < 15u)
                    row2[j] = p + d2;
            }
        }

        float acc[4][4];
#pragma unroll
        for (int u = 0; u < 4; u++)
#pragma unroll
            for (int j = 0; j < 4; j++) acc[u][j] = 0.f;

#pragma unroll
        for (int t = 0; t < NTAPS; t++) {
            const float4* w4p = reinterpret_cast<const float4*>(w + t*TAPSTRIDE);
            int pb[4], px[4];
#pragma unroll
            for (int j = 0; j < 4; j++) {
                int r = (NTAPS == 3)
                      ? (t == 0 ? row0[j] : (t == 1 ? rowv[j] : row2[j]))
                      : rowv[j];
                pb[j] = r * 32;
                px[j] = r & 7;
            }

#pragma unroll 2
            for (int c4 = 0; c4 < 32; c4++) {
                float4 w4[4];
#pragma unroll
                for (int u = 0; u < 4; u++)
                    w4[u] = w4p[(ob+u)*32 + c4];
                float4 vv[4];
#pragma unroll
                for (int j = 0; j < 4; j++)
                    vv[j] = s4in[pb[j] + (c4 ^ px[j])];
#pragma unroll
                for (int u = 0; u < 4; u++) {
#pragma unroll
                    for (int j = 0; j < 4; j++) {
                        acc[u][j] = fmaf(w4[u].x, vv[j].x, acc[u][j]);
                        acc[u][j] = fmaf(w4[u].y, vv[j].y, acc[u][j]);
                        acc[u][j] = fmaf(w4[u].z, vv[j].z, acc[u][j]);
                        acc[u][j] = fmaf(w4[u].w, vv[j].w, acc[u][j]);
                    }
                }
            }
        }

#pragma unroll
        for (int j = 0; j < 4; j++) {
            if (!wrv[j]) continue;
            float4 val;
            val.x = acc[0][j] + b4[0];
            val.y = acc[1][j] + b4[1];
            val.z = acc[2][j] + b4[2];
            val.w = acc[3][j] + b4[3];
            if (ACT) {
                val.x = silu_f(val.x); val.y = silu_f(val.y);
                val.z = silu_f(val.z); val.w = silu_f(val.w);
            }
            if (RESID) {
                float4 r4 = s4res[gran(rowv[j], obc4)];
                val.x += r4.x; val.y += r4.y; val.z += r4.z; val.w += r4.w;
            }
            if (TOGLOBAL) {
                gout[(ob+0)*HW + rowv[j]] = val.x;
                gout[(ob+1)*HW + rowv[j]] = val.y;
                gout[(ob+2)*HW + rowv[j]] = val.z;
                gout[(ob+3)*HW + rowv[j]] = val.w;
            } else {
                s4out[gran(rowv[j], obc4)] = val;
            }
        }
    }
}

__global__ void __launch_bounds__(512, 1)
mix9s_kernel(const float* __restrict__ x,
             const float* __restrict__ dw0, const float* __restrict__ db0,
             const float* __restrict__ rdb,
             const float* __restrict__ rpw, const float* __restrict__ rpb,
             const float* __restrict__ cw1, const float* __restrict__ cb1,
             const float* __restrict__ cw2, const float* __restrict__ cb2,
             const float* __restrict__ fw,  const float* __restrict__ fb,
             float* __restrict__ out)
{
    extern __shared__ float smem[];
    float* bufA = smem;                     // swizzled [226][128]
    float* bufB = smem + NROWS*NCH;
    float4* a4 = reinterpret_cast<float4*>(bufA);
    float4* b4 = reinterpret_cast<float4*>(bufB);

    const int tid = threadIdx.x;
    const int b = blockIdx.x & 255;
    const int d = blockIdx.x >> 8;
    const int di0 = c_DI0[d], dj0 = c_DJ0[d], di2 = c_DI2[d], dj2 = c_DJ2[d];

    // zero rows (entire 128-float row; swizzle only permutes within the row)
    if (tid < NCH) {
        bufA[ZROW*NCH + tid] = 0.f;
        bufB[ZROW*NCH + tid] = 0.f;
    }
    // stage x (2 channels) into bufB swizzled: channels 0,1 live in granule c4=0
    const float* xb = x + b*(2*HW);
    for (int idx = tid; idx < 2*HW; idx += 512) {
        int c = idx / HW;
        int p = idx - c*HW;
        bufB[gran(p, 0)*4 + c] = xb[idx];
    }
    __syncthreads();

    // ---- dconv0: Cin=2, 3 taps, silu -> bufA ----
    {
        const int oz = tid >> 4, pl = tid & 15;
        const int ob = oz * 4;
        float wr_[4][2][3];
#pragma unroll
        for (int u = 0; u < 4; u++)
#pragma unroll
            for (int c = 0; c < 2; c++)
#pragma unroll
                for (int t = 0; t < 3; t++)
                    wr_[u][c][t] = dw0[((ob+u)*2 + c)*3 + t];
        float bb[4];
#pragma unroll
        for (int u = 0; u < 4; u++) bb[u] = db0[ob+u];

        const int d0 = di0*15 + dj0;
        const int d2 = di2*15 + dj2;
#pragma unroll 1
        for (int ch = 0; ch < 4; ch++) {
#pragma unroll
            for (int j = 0; j < 4; j++) {
                int p = pl + 16*(ch*4 + j);
                bool v = p < HW;
                int rv = v ? p : ZROW;
                int r0 = ZROW, r2 = ZROW;
                int pi = p / 15, pj = p - pi*15;
                if (v && (unsigned)(pi+di0) < 15u && (unsigned)(pj+dj0) < 15u)
                    r0 = p + d0;
                if (v && (unsigned)(pi+di2) < 15u && (unsigned)(pj+dj2) < 15u)
                    r2 = p + d2;

                float v0[2], vc[2], v2[2];
#pragma unroll
                for (int c = 0; c < 2; c++) {
                    v0[c] = bufB[gran(r0, 0)*4 + c];
                    vc[c] = bufB[gran(rv, 0)*4 + c];
                    v2[c] = bufB[gran(r2, 0)*4 + c];
                }
                if (v) {
                    float4 val;
                    float res[4];
#pragma unroll
                    for (int u = 0; u < 4; u++) {
                        float a = bb[u];
#pragma unroll
                        for (int c = 0; c < 2; c++) {
                            a = fmaf(wr_[u][c][0], v0[c], a);
                            a = fmaf(wr_[u][c][1], vc[c], a);
                            a = fmaf(wr_[u][c][2], v2[c], a);
                        }
                        res[u] = silu_f(a);
                    }
                    val.x = res[0]; val.y = res[1]; val.z = res[2]; val.w = res[3];
                    a4[gran(rv, oz)] = val;
                }
            }
        }
    }
    __syncthreads();

    // ---- 4 directional res blocks ----
#pragma unroll 1
    for (int i = 0; i < 4; i++) {
        layer_c128<3, true, false, false>(a4, b4, nullptr,
            g_dwt + i*3*TAPSTRIDE, rdb + i*128, nullptr, di0, dj0, di2, dj2);
        __syncthreads();
        layer_c128<1, true, true, false>(b4, a4, nullptr,
            rpw + i*TAPSTRIDE, rpb + i*128, a4, 0, 0, 0, 0);
        __syncthreads();
    }

    // ---- Conv0d res block (two 1x1, residual) ----
    layer_c128<1, true, false, false>(a4, b4, nullptr, cw1, cb1, nullptr, 0,0,0,0);
    __syncthreads();
    layer_c128<1, true, true, false>(b4, a4, nullptr, cw2, cb2, a4, 0,0,0,0);
    __syncthreads();

    // ---- final 1x1 (128 -> 64), no activation, straight to global ----
    layer_c128<1, false, false, true>(a4, nullptr, out + (b*4 + d)*64*HW,
                                      fw, fb, nullptr, 0,0,0,0);
}

extern "C" void kernel_launch(void* const* d_in, const int* in_sizes, int n_in,
                              void* d_out, int out_size) {
    (void)in_sizes; (void)n_in; (void)out_size;
    const float* x   = (const float*)d_in[0];
    const float* dw0 = (const float*)d_in[1];
    const float* db0 = (const float*)d_in[2];
    const float* rdw = (const float*)d_in[3];
    const float* rdb = (const float*)d_in[4];
    const float* rpw = (const float*)d_in[5];
    const float* rpb = (const float*)d_in[6];
    const float* cw1 = (const float*)d_in[7];
    const float* cb1 = (const float*)d_in[8];
    const float* cw2 = (const float*)d_in[9];
    const float* cb2 = (const float*)d_in[10];
    const float* fw  = (const float*)d_in[11];
    const float* fb  = (const float*)d_in[12];
    float* out = (float*)d_out;

    cudaFuncSetAttribute(mix9s_kernel,
                         cudaFuncAttributeMaxDynamicSharedMemorySize, SMEM_BYTES);

    prep_kernel<<<768, 256>>>(rdw);
    mix9s_kernel<<<1024, 512, SMEM_BYTES>>>(
        x, dw0, db0, rdb, rpw, rpb, cw1, cb1, cw2, cb2, fw, fb, out);
}

// round 5
// speedup vs baseline: 1.2858x; 1.2399x over previous
#include <cuda_runtime.h>

#define HW 225
#define ZROW 225          // guaranteed-zero row (all 128 channels zero)
#define NROWS 226
#define NCH 128
#define TAPSTRIDE (128*128)
#define SMEM_FLOATS (2*NROWS*NCH)
#define SMEM_BYTES (SMEM_FLOATS*4)

// per-direction tap offsets: d0 horiz, d1 vert, d2 anti-diag, d3 main diag
__constant__ int c_DI0[4] = { 0,-1, 1,-1};
__constant__ int c_DJ0[4] = {-1, 0,-1,-1};
__constant__ int c_DI2[4] = { 0, 1,-1, 1};
__constant__ int c_DJ2[4] = { 1, 0, 1, 1};

// transposed res dconv weights: [i][t][o][c] (c contiguous for LDG.128)
__device__ __align__(16) float g_dwt[4*3*128*128];

__global__ void prep_kernel(const float* __restrict__ w) {
    const int n = 4*3*128*128;
    for (int idx = blockIdx.x*blockDim.x + threadIdx.x; idx < n;
         idx += gridDim.x*blockDim.x) {
        int c = idx & 127;
        int r = idx >> 7;
        int o = r & 127;
        r >>= 7;            // r = i*3 + t
        int t = r % 3;
        int i = r / 3;
        g_dwt[idx] = w[((i*128 + o)*128 + c)*3 + t];
    }
}

__device__ __forceinline__ float silu_f(float x) {
    return x * (1.0f / (1.0f + __expf(-x)));
}

// swizzled 16B-granule index for smem layout [row p][128 channels]
// granule (p, c4) -> p*32 + (c4 ^ (p&7)); 8 consecutive p (one LDS.128 phase)
// hit 8 distinct 16B bank-groups -> conflict-free.
__device__ __forceinline__ int gran(int p, int c4) {
    return p*32 + (c4 ^ (p & 7));
}

// Smem->smem layer over Cin=128.
// Partition: 16 oz-groups (8 outputs each) x 32 position lanes; 2 chunks x 4 j.
// Within a warp all lanes share one oz-group -> weight LDG is uniform/broadcast.
template<int NTAPS, bool ACT, bool RESID>
__device__ __forceinline__ void layer_c128(
    const float4* __restrict__ s4in,
    float4* s4out,
    const float* __restrict__ w,    // [NTAPS][Co][128], c contiguous
    const float* __restrict__ bias,
    const float4* s4res,
    int di0, int dj0, int di2, int dj2)
{
    const int tid = threadIdx.x;
    const int oz = tid >> 5;            // 0..15
    const int pl = tid & 31;
    const int ob = oz * 8;
    const int g0 = oz * 2;              // output granules g0, g0+1

    float b8[8];
#pragma unroll
    for (int u = 0; u < 8; u++) b8[u] = bias[ob + u];

    const int d0 = di0*15 + dj0;
    const int d2 = di2*15 + dj2;

#pragma unroll 1
    for (int ch = 0; ch < 2; ch++) {
        int rowv[4], row0[4], row2[4];
        bool wrv[4];
#pragma unroll
        for (int j = 0; j < 4; j++) {
            int p = pl + 32*(ch*4 + j);
            bool v = p < HW;
            wrv[j] = v;
            rowv[j] = v ? p : ZROW;
            row0[j] = ZROW; row2[j] = ZROW;
            if (NTAPS == 3) {
                int pi = p / 15, pj = p - pi*15;
                if (v && (unsigned)(pi+di0) < 15u && (unsigned)(pj+dj0) < 15u)
                    row0[j] = p + d0;
                if (v && (unsigned)(pi+di2) < 15u && (unsigned)(pj+dj2) < 15u)
                    row2[j] = p + d2;
            }
        }

        float acc[8][4];
#pragma unroll
        for (int u = 0; u < 8; u++)
#pragma unroll
            for (int j = 0; j < 4; j++) acc[u][j] = 0.f;

#pragma unroll
        for (int t = 0; t < NTAPS; t++) {
            const float4* w4p = reinterpret_cast<const float4*>(w + t*TAPSTRIDE);
            int pb[4], px[4];
#pragma unroll
            for (int j = 0; j < 4; j++) {
                int r = (NTAPS == 3)
                      ? (t == 0 ? row0[j] : (t == 1 ? rowv[j] : row2[j]))
                      : rowv[j];
                pb[j] = r * 32;
                px[j] = r & 7;
            }

#pragma unroll 2
            for (int c4 = 0; c4 < 32; c4++) {
                float4 w4[8];
#pragma unroll
                for (int u = 0; u < 8; u++)
                    w4[u] = w4p[(ob+u)*32 + c4];
                float4 vv[4];
#pragma unroll
                for (int j = 0; j < 4; j++)
                    vv[j] = s4in[pb[j] + (c4 ^ px[j])];
#pragma unroll
                for (int u = 0; u < 8; u++) {
#pragma unroll
                    for (int j = 0; j < 4; j++) {
                        acc[u][j] = fmaf(w4[u].x, vv[j].x, acc[u][j]);
                        acc[u][j] = fmaf(w4[u].y, vv[j].y, acc[u][j]);
                        acc[u][j] = fmaf(w4[u].z, vv[j].z, acc[u][j]);
                        acc[u][j] = fmaf(w4[u].w, vv[j].w, acc[u][j]);
                    }
                }
            }
        }

#pragma unroll
        for (int j = 0; j < 4; j++) {
            if (!wrv[j]) continue;
            float4 lo, hi;
            lo.x = acc[0][j] + b8[0];  lo.y = acc[1][j] + b8[1];
            lo.z = acc[2][j] + b8[2];  lo.w = acc[3][j] + b8[3];
            hi.x = acc[4][j] + b8[4];  hi.y = acc[5][j] + b8[5];
            hi.z = acc[6][j] + b8[6];  hi.w = acc[7][j] + b8[7];
            if (ACT) {
                lo.x = silu_f(lo.x); lo.y = silu_f(lo.y);
                lo.z = silu_f(lo.z); lo.w = silu_f(lo.w);
                hi.x = silu_f(hi.x); hi.y = silu_f(hi.y);
                hi.z = silu_f(hi.z); hi.w = silu_f(hi.w);
            }
            if (RESID) {
                float4 r0 = s4res[gran(rowv[j], g0)];
                float4 r1 = s4res[gran(rowv[j], g0+1)];
                lo.x += r0.x; lo.y += r0.y; lo.z += r0.z; lo.w += r0.w;
                hi.x += r1.x; hi.y += r1.y; hi.z += r1.z; hi.w += r1.w;
            }
            s4out[gran(rowv[j], g0)]   = lo;
            s4out[gran(rowv[j], g0+1)] = hi;
        }
    }
}

// Final 1x1 (128 -> 64) straight to global. 16 oz-groups x 4 outputs,
// 8 positions per thread. Uniform weight loads within a warp.
__device__ __forceinline__ void final_layer(
    const float4* __restrict__ s4in,
    float* gout,
    const float* __restrict__ w,
    const float* __restrict__ bias)
{
    const int tid = threadIdx.x;
    const int oz = tid >> 5;            // 0..15
    const int pl = tid & 31;
    const int ob = oz * 4;

    float b4[4];
#pragma unroll
    for (int u = 0; u < 4; u++) b4[u] = bias[ob + u];

    int rowv[8]; bool wrv[8];
#pragma unroll
    for (int j = 0; j < 8; j++) {
        int p = pl + 32*j;
        wrv[j] = p < HW;
        rowv[j] = wrv[j] ? p : ZROW;
    }

    float acc[4][8];
#pragma unroll
    for (int u = 0; u < 4; u++)
#pragma unroll
        for (int j = 0; j < 8; j++) acc[u][j] = 0.f;

    const float4* w4p = reinterpret_cast<const float4*>(w);
#pragma unroll 2
    for (int c4 = 0; c4 < 32; c4++) {
        float4 w4[4];
#pragma unroll
        for (int u = 0; u < 4; u++)
            w4[u] = w4p[(ob+u)*32 + c4];
        float4 vv[8];
#pragma unroll
        for (int j = 0; j < 8; j++)
            vv[j] = s4in[rowv[j]*32 + (c4 ^ (rowv[j] & 7))];
#pragma unroll
        for (int u = 0; u < 4; u++) {
#pragma unroll
            for (int j = 0; j < 8; j++) {
                acc[u][j] = fmaf(w4[u].x, vv[j].x, acc[u][j]);
                acc[u][j] = fmaf(w4[u].y, vv[j].y, acc[u][j]);
                acc[u][j] = fmaf(w4[u].z, vv[j].z, acc[u][j]);
                acc[u][j] = fmaf(w4[u].w, vv[j].w, acc[u][j]);
            }
        }
    }

#pragma unroll
    for (int u = 0; u < 4; u++) {
#pragma unroll
        for (int j = 0; j < 8; j++) {
            if (wrv[j]) gout[(ob+u)*HW + rowv[j]] = acc[u][j] + b4[u];
        }
    }
}

__global__ void __launch_bounds__(512, 1)
mix9s_kernel(const float* __restrict__ x,
             const float* __restrict__ dw0, const float* __restrict__ db0,
             const float* __restrict__ rdb,
             const float* __restrict__ rpw, const float* __restrict__ rpb,
             const float* __restrict__ cw1, const float* __restrict__ cb1,
             const float* __restrict__ cw2, const float* __restrict__ cb2,
             const float* __restrict__ fw,  const float* __restrict__ fb,
             float* __restrict__ out)
{
    extern __shared__ float smem[];
    float* bufA = smem;                     // swizzled [226][128]
    float* bufB = smem + NROWS*NCH;
    float4* a4 = reinterpret_cast<float4*>(bufA);
    float4* b4 = reinterpret_cast<float4*>(bufB);

    const int tid = threadIdx.x;
    const int b = blockIdx.x & 255;
    const int d = blockIdx.x >> 8;
    const int di0 = c_DI0[d], dj0 = c_DJ0[d], di2 = c_DI2[d], dj2 = c_DJ2[d];

    // zero rows (entire 128-float row; swizzle only permutes within the row)
    if (tid < NCH) {
        bufA[ZROW*NCH + tid] = 0.f;
        bufB[ZROW*NCH + tid] = 0.f;
    }
    // stage x (2 channels) into bufB: channels 0,1 live in granule c4=0
    const float* xb = x + b*(2*HW);
    for (int idx = tid; idx < 2*HW; idx += 512) {
        int c = idx / HW;
        int p = idx - c*HW;
        bufB[gran(p, 0)*4 + c] = xb[idx];
    }
    __syncthreads();

    // ---- dconv0: Cin=2, 3 taps, silu -> bufA ----
    {
        const int oz = tid >> 4, pl = tid & 15;   // 32 groups x 4 outputs
        const int ob = oz * 4;
        float wr_[4][2][3];
#pragma unroll
        for (int u = 0; u < 4; u++)
#pragma unroll
            for (int c = 0; c < 2; c++)
#pragma unroll
                for (int t = 0; t < 3; t++)
                    wr_[u][c][t] = dw0[((ob+u)*2 + c)*3 + t];
        float bb[4];
#pragma unroll
        for (int u = 0; u < 4; u++) bb[u] = db0[ob+u];

        const int d0 = di0*15 + dj0;
        const int d2 = di2*15 + dj2;
#pragma unroll 1
        for (int ch = 0; ch < 4; ch++) {
#pragma unroll
            for (int j = 0; j < 4; j++) {
                int p = pl + 16*(ch*4 + j);
                bool v = p < HW;
                int rv = v ? p : ZROW;
                int r0 = ZROW, r2 = ZROW;
                int pi = p / 15, pj = p - pi*15;
                if (v && (unsigned)(pi+di0) < 15u && (unsigned)(pj+dj0) < 15u)
                    r0 = p + d0;
                if (v && (unsigned)(pi+di2) < 15u && (unsigned)(pj+dj2) < 15u)
                    r2 = p + d2;

                float v0[2], vc[2], v2[2];
#pragma unroll
                for (int c = 0; c < 2; c++) {
                    v0[c] = bufB[gran(r0, 0)*4 + c];
                    vc[c] = bufB[gran(rv, 0)*4 + c];
                    v2[c] = bufB[gran(r2, 0)*4 + c];
                }
                if (v) {
                    float4 val;
                    float res[4];
#pragma unroll
                    for (int u = 0; u < 4; u++) {
                        float a = bb[u];
#pragma unroll
                        for (int c = 0; c < 2; c++) {
                            a = fmaf(wr_[u][c][0], v0[c], a);
                            a = fmaf(wr_[u][c][1], vc[c], a);
                            a = fmaf(wr_[u][c][2], v2[c], a);
                        }
                        res[u] = silu_f(a);
                    }
                    val.x = res[0]; val.y = res[1]; val.z = res[2]; val.w = res[3];
                    a4[gran(rv, oz)] = val;
                }
            }
        }
    }
    __syncthreads();

    // ---- 4 directional res blocks ----
#pragma unroll 1
    for (int i = 0; i < 4; i++) {
        layer_c128<3, true, false>(a4, b4,
            g_dwt + i*3*TAPSTRIDE, rdb + i*128, nullptr, di0, dj0, di2, dj2);
        __syncthreads();
        layer_c128<1, true, true>(b4, a4,
            rpw + i*TAPSTRIDE, rpb + i*128, a4, 0, 0, 0, 0);
        __syncthreads();
    }

    // ---- Conv0d res block (two 1x1, residual) ----
    layer_c128<1, true, false>(a4, b4, cw1, cb1, nullptr, 0,0,0,0);
    __syncthreads();
    layer_c128<1, true, true>(b4, a4, cw2, cb2, a4, 0,0,0,0);
    __syncthreads();

    // ---- final 1x1 (128 -> 64), no activation, straight to global ----
    final_layer(a4, out + (b*4 + d)*64*HW, fw, fb);
}

extern "C" void kernel_launch(void* const* d_in, const int* in_sizes, int n_in,
                              void* d_out, int out_size) {
    (void)in_sizes; (void)n_in; (void)out_size;
    const float* x   = (const float*)d_in[0];
    const float* dw0 = (const float*)d_in[1];
    const float* db0 = (const float*)d_in[2];
    const float* rdw = (const float*)d_in[3];
    const float* rdb = (const float*)d_in[4];
    const float* rpw = (const float*)d_in[5];
    const float* rpb = (const float*)d_in[6];
    const float* cw1 = (const float*)d_in[7];
    const float* cb1 = (const float*)d_in[8];
    const float* cw2 = (const float*)d_in[9];
    const float* cb2 = (const float*)d_in[10];
    const float* fw  = (const float*)d_in[11];
    const float* fb  = (const float*)d_in[12];
    float* out = (float*)d_out;

    cudaFuncSetAttribute(mix9s_kernel,
                         cudaFuncAttributeMaxDynamicSharedMemorySize, SMEM_BYTES);

    prep_kernel<<<768, 256>>>(rdw);
    mix9s_kernel<<<1024, 512, SMEM_BYTES>>>(
        x, dw0, db0, rdb, rpw, rpb, cw1, cb1, cw2, cb2, fw, fb, out);
}

// round 6
// speedup vs baseline: 2.7551x; 2.1427x over previous
#include <cuda_runtime.h>
#include <cuda_fp16.h>

#define HW 225
#define ZROW 225          // guaranteed-zero row (all 128 channels zero)
#define NROWS 226
#define NCH 128
#define SMEM_FLOATS (2*NROWS*NCH)
#define SMEM_BYTES (SMEM_FLOATS*4)

// per-direction tap offsets: d0 horiz, d1 vert, d2 anti-diag, d3 main diag
__constant__ int c_DI0[4] = { 0,-1, 1,-1};
__constant__ int c_DJ0[4] = {-1, 0,-1,-1};
__constant__ int c_DI2[4] = { 0, 1,-1, 1};
__constant__ int c_DJ2[4] = { 1, 0, 1, 1};

// ---- f16 weight arena (halves) ----
// dir:  [i][t][o][c]      4*3*128*128 = 196608
// pw:   [i][o][c]         4*128*128   =  65536
// c1:   [o][c]                          16384
// c2:   [o][c]                          16384
// fin:  [o][c] (64x128)                  8192
#define WOFF_DIR 0
#define WOFF_PW  196608
#define WOFF_C1  262144
#define WOFF_C2  278528
#define WOFF_FIN 294912
#define WTOTAL   303104
__device__ __align__(16) __half g_wh[WTOTAL];

__global__ void prep_kernel(const float* __restrict__ rdw,
                            const float* __restrict__ rpw,
                            const float* __restrict__ cw1,
                            const float* __restrict__ cw2,
                            const float* __restrict__ fw) {
    for (int idx = blockIdx.x*blockDim.x + threadIdx.x; idx < WTOTAL;
         idx += gridDim.x*blockDim.x) {
        float v;
        if (idx < WOFF_PW) {
            // dest ((i*3+t)*128+o)*128+c  <- rdw[((i*128+o)*128+c)*3 + t]
            int c = idx & 127;
            int o = (idx >> 7) & 127;
            int r = idx >> 14;          // i*3 + t
            int t = r % 3;
            int i = r / 3;
            v = rdw[((i*128 + o)*128 + c)*3 + t];
        } else if (idx < WOFF_C1) {
            v = rpw[idx - WOFF_PW];
        } else if (idx < WOFF_C2) {
            v = cw1[idx - WOFF_C1];
        } else if (idx < WOFF_FIN) {
            v = cw2[idx - WOFF_C2];
        } else {
            v = fw[idx - WOFF_FIN];
        }
        g_wh[idx] = __float2half(v);
    }
}

__device__ __forceinline__ float silu_f(float x) {
    return x * (1.0f / (1.0f + __expf(-x)));
}

// swizzled granule index: (p, c4) -> p*32 + (c4 ^ (p&7)); float idx of (p,o):
__device__ __forceinline__ int sidx(int p, int o) {
    return p*128 + (((o >> 2) ^ (p & 7)) << 2) + (o & 3);
}

__device__ __forceinline__ void mma_16816(float* d,
    unsigned a0, unsigned a1, unsigned a2, unsigned a3,
    unsigned b0, unsigned b1)
{
    asm volatile(
        "mma.sync.aligned.m16n8k16.row.col.f32.f16.f16.f32 "
        "{%0,%1,%2,%3}, {%4,%5,%6,%7}, {%8,%9}, {%0,%1,%2,%3};\n"
        : "+f"(d[0]), "+f"(d[1]), "+f"(d[2]), "+f"(d[3])
        : "r"(a0), "r"(a1), "r"(a2), "r"(a3), "r"(b0), "r"(b1));
}

// MMA layer, Cin=128 -> Co=128.  16 warps = 8 out-groups(16) x 2 pos-cols.
// Each warp: 2 passes x 8 n-tiles (8 positions each): covers 128 pos/warp-col.
// Weights: f16 [NTAPS][128][128] (c contiguous).  Activations fp32 in smem,
// packed to half2 at load.  Accumulate fp32.
template<int NTAPS, bool ACT, bool RESID>
__device__ __forceinline__ void layer_mma(
    const float* __restrict__ sin,
    float* __restrict__ sout,
    const __half* __restrict__ wh,
    const float* __restrict__ bias,
    const float* __restrict__ sres,
    int di0, int dj0, int di2, int dj2)
{
    const int tid  = threadIdx.x;
    const int wid  = tid >> 5;
    const int lane = tid & 31;
    const int tg = lane >> 2, tk = lane & 3;
    const int oz = wid >> 1, pc = wid & 1;
    const int ob = oz * 16;
    const float bias0 = bias[ob + tg];
    const float bias1 = bias[ob + tg + 8];
    const unsigned* w32 = reinterpret_cast<const unsigned*>(wh);
    const int wbase0 = (ob + tg)*64 + tk;      // uint units, row stride 64
    const char* sb = reinterpret_cast<const char*>(sin);
    const int boff = (tk & 1)*8;               // byte offset of b0 pair in granule
    const int kg = tk >> 1;

#pragma unroll 1
    for (int q = 0; q < 2; q++) {
        const int pbase = pc*128 + q*64;
        float acc[8][4];
#pragma unroll
        for (int i = 0; i < 8; i++)
#pragma unroll
            for (int u = 0; u < 4; u++) acc[i][u] = 0.f;

#pragma unroll
        for (int tap = 0; tap < NTAPS; tap++) {
            int di = 0, dj = 0;
            if (NTAPS == 3) {
                di = (tap == 0) ? di0 : ((tap == 1) ? 0 : di2);
                dj = (tap == 0) ? dj0 : ((tap == 1) ? 0 : dj2);
            }
            int baseB[8], rx[8];
#pragma unroll
            for (int i = 0; i < 8; i++) {
                int p = pbase + i*8 + tg;
                int r = ZROW;
                if (p < HW) {
                    if (NTAPS == 3 && tap != 1) {
                        int pi = p / 15, pj = p - pi*15;
                        if ((unsigned)(pi + di) < 15u && (unsigned)(pj + dj) < 15u)
                            r = p + di*15 + dj;
                    } else {
                        r = p;
                    }
                }
                baseB[i] = r*512 + boff;
                rx[i] = r & 7;
            }
            const unsigned* wt32 = w32 + tap*8192;

#pragma unroll 1
            for (int s = 0; s < 8; s++) {
                unsigned a0 = wt32[wbase0 + 8*s];
                unsigned a1 = wt32[wbase0 + 512 + 8*s];
                unsigned a2 = wt32[wbase0 + 8*s + 4];
                unsigned a3 = wt32[wbase0 + 512 + 8*s + 4];
                int x0 = 4*s + kg;
#pragma unroll
                for (int i = 0; i < 8; i++) {
                    float2 f0 = *reinterpret_cast<const float2*>(
                        sb + baseB[i] + ((x0 ^ rx[i]) << 4));
                    float2 f1 = *reinterpret_cast<const float2*>(
                        sb + baseB[i] + (((x0 + 2) ^ rx[i]) << 4));
                    __half2 h0 = __floats2half2_rn(f0.x, f0.y);
                    __half2 h1 = __floats2half2_rn(f1.x, f1.y);
                    mma_16816(acc[i], a0, a1, a2, a3,
                              *reinterpret_cast<unsigned*>(&h0),
                              *reinterpret_cast<unsigned*>(&h1));
                }
            }
        }

        // epilogue: thread owns (o0,o1) x (p0,p1) per tile
        const int o0 = ob + tg, o1 = o0 + 8;
#pragma unroll
        for (int i = 0; i < 8; i++) {
            int p0 = pbase + i*8 + tk*2;
            int p1 = p0 + 1;
            float v00 = acc[i][0] + bias0;
            float v01 = acc[i][1] + bias0;
            float v10 = acc[i][2] + bias1;
            float v11 = acc[i][3] + bias1;
            if (ACT) {
                v00 = silu_f(v00); v01 = silu_f(v01);
                v10 = silu_f(v10); v11 = silu_f(v11);
            }
            if (p0 < HW) {
                int i00 = sidx(p0, o0), i10 = sidx(p0, o1);
                if (RESID) { v00 += sres[i00]; v10 += sres[i10]; }
                sout[i00] = v00; sout[i10] = v10;
            }
            if (p1 < HW) {
                int i01 = sidx(p1, o0), i11 = sidx(p1, o1);
                if (RESID) { v01 += sres[i01]; v11 += sres[i11]; }
                sout[i01] = v01; sout[i11] = v11;
            }
        }
    }
}

// Final 1x1, 128 -> 64, to global.  16 warps = 4 out-groups(16) x 4 pos-cols(64).
__device__ __forceinline__ void final_mma(
    const float* __restrict__ sin,
    float* __restrict__ gout,
    const __half* __restrict__ wh,
    const float* __restrict__ bias)
{
    const int tid  = threadIdx.x;
    const int wid  = tid >> 5;
    const int lane = tid & 31;
    const int tg = lane >> 2, tk = lane & 3;
    const int oz = wid >> 2, pc = wid & 3;
    const int ob = oz * 16;
    const int pbase = pc * 64;
    const float bias0 = bias[ob + tg];
    const float bias1 = bias[ob + tg + 8];
    const unsigned* w32 = reinterpret_cast<const unsigned*>(wh);
    const int wbase0 = (ob + tg)*64 + tk;
    const char* sb = reinterpret_cast<const char*>(sin);
    const int boff = (tk & 1)*8;
    const int kg = tk >> 1;

    float acc[8][4];
#pragma unroll
    for (int i = 0; i < 8; i++)
#pragma unroll
        for (int u = 0; u < 4; u++) acc[i][u] = 0.f;

    int baseB[8], rx[8];
#pragma unroll
    for (int i = 0; i < 8; i++) {
        int p = pbase + i*8 + tg;
        int r = (p < HW) ? p : ZROW;
        baseB[i] = r*512 + boff;
        rx[i] = r & 7;
    }

#pragma unroll 1
    for (int s = 0; s < 8; s++) {
        unsigned a0 = w32[wbase0 + 8*s];
        unsigned a1 = w32[wbase0 + 512 + 8*s];
        unsigned a2 = w32[wbase0 + 8*s + 4];
        unsigned a3 = w32[wbase0 + 512 + 8*s + 4];
        int x0 = 4*s + kg;
#pragma unroll
        for (int i = 0; i < 8; i++) {
            float2 f0 = *reinterpret_cast<const float2*>(
                sb + baseB[i] + ((x0 ^ rx[i]) << 4));
            float2 f1 = *reinterpret_cast<const float2*>(
                sb + baseB[i] + (((x0 + 2) ^ rx[i]) << 4));
            __half2 h0 = __floats2half2_rn(f0.x, f0.y);
            __half2 h1 = __floats2half2_rn(f1.x, f1.y);
            mma_16816(acc[i], a0, a1, a2, a3,
                      *reinterpret_cast<unsigned*>(&h0),
                      *reinterpret_cast<unsigned*>(&h1));
        }
    }

    const int o0 = ob + tg, o1 = o0 + 8;
#pragma unroll
    for (int i = 0; i < 8; i++) {
        int p0 = pbase + i*8 + tk*2;
        int p1 = p0 + 1;
        if (p0 < HW) {
            gout[o0*HW + p0] = acc[i][0] + bias0;
            gout[o1*HW + p0] = acc[i][2] + bias1;
        }
        if (p1 < HW) {
            gout[o0*HW + p1] = acc[i][1] + bias0;
            gout[o1*HW + p1] = acc[i][3] + bias1;
        }
    }
}

__global__ void __launch_bounds__(512, 1)
mix9s_kernel(const float* __restrict__ x,
             const float* __restrict__ dw0, const float* __restrict__ db0,
             const float* __restrict__ rdb, const float* __restrict__ rpb,
             const float* __restrict__ cb1, const float* __restrict__ cb2,
             const float* __restrict__ fb,
             float* __restrict__ out)
{
    extern __shared__ float smem[];
    float* bufA = smem;                     // swizzled [226][128]
    float* bufB = smem + NROWS*NCH;

    const int tid = threadIdx.x;
    const int b = blockIdx.x & 255;
    const int d = blockIdx.x >> 8;
    const int di0 = c_DI0[d], dj0 = c_DJ0[d], di2 = c_DI2[d], dj2 = c_DJ2[d];

    // zero rows
    if (tid < NCH) {
        bufA[ZROW*NCH + tid] = 0.f;
        bufB[ZROW*NCH + tid] = 0.f;
    }
    // stage x (2 channels) into bufB: channels 0,1 in granule c4=0
    const float* xb = x + b*(2*HW);
    for (int idx = tid; idx < 2*HW; idx += 512) {
        int c = idx / HW;
        int p = idx - c*HW;
        bufB[sidx(p, c)] = xb[idx];
    }
    __syncthreads();

    // ---- dconv0: Cin=2, 3 taps, silu -> bufA (scalar; tiny) ----
    {
        const int oz = tid >> 4, pl = tid & 15;   // 32 groups x 4 outputs
        const int ob = oz * 4;
        float wr_[4][2][3];
#pragma unroll
        for (int u = 0; u < 4; u++)
#pragma unroll
            for (int c = 0; c < 2; c++)
#pragma unroll
                for (int t = 0; t < 3; t++)
                    wr_[u][c][t] = dw0[((ob+u)*2 + c)*3 + t];
        float bb[4];
#pragma unroll
        for (int u = 0; u < 4; u++) bb[u] = db0[ob+u];

        const int d0 = di0*15 + dj0;
        const int d2 = di2*15 + dj2;
#pragma unroll 1
        for (int ch = 0; ch < 4; ch++) {
#pragma unroll
            for (int j = 0; j < 4; j++) {
                int p = pl + 16*(ch*4 + j);
                bool v = p < HW;
                int rv = v ? p : ZROW;
                int r0 = ZROW, r2 = ZROW;
                int pi = p / 15, pj = p - pi*15;
                if (v && (unsigned)(pi+di0) < 15u && (unsigned)(pj+dj0) < 15u)
                    r0 = p + d0;
                if (v && (unsigned)(pi+di2) < 15u && (unsigned)(pj+dj2) < 15u)
                    r2 = p + d2;

                float v0[2], vc[2], v2[2];
#pragma unroll
                for (int c = 0; c < 2; c++) {
                    v0[c] = bufB[sidx(r0, c)];
                    vc[c] = bufB[sidx(rv, c)];
                    v2[c] = bufB[sidx(r2, c)];
                }
                if (v) {
#pragma unroll
                    for (int u = 0; u < 4; u++) {
                        float a = bb[u];
#pragma unroll
                        for (int c = 0; c < 2; c++) {
                            a = fmaf(wr_[u][c][0], v0[c], a);
                            a = fmaf(wr_[u][c][1], vc[c], a);
                            a = fmaf(wr_[u][c][2], v2[c], a);
                        }
                        bufA[sidx(rv, ob+u)] = silu_f(a);
                    }
                }
            }
        }
    }
    __syncthreads();

    // ---- 4 directional res blocks ----
#pragma unroll 1
    for (int i = 0; i < 4; i++) {
        layer_mma<3, true, false>(bufA, bufB,
            g_wh + WOFF_DIR + i*3*16384, rdb + i*128, nullptr,
            di0, dj0, di2, dj2);
        __syncthreads();
        layer_mma<1, true, true>(bufB, bufA,
            g_wh + WOFF_PW + i*16384, rpb + i*128, bufA, 0, 0, 0, 0);
        __syncthreads();
    }

    // ---- Conv0d res block (two 1x1, residual) ----
    layer_mma<1, true, false>(bufA, bufB, g_wh + WOFF_C1, cb1, nullptr, 0,0,0,0);
    __syncthreads();
    layer_mma<1, true, true>(bufB, bufA, g_wh + WOFF_C2, cb2, bufA, 0,0,0,0);
    __syncthreads();

    // ---- final 1x1 (128 -> 64), no activation, straight to global ----
    final_mma(bufA, out + (b*4 + d)*64*HW, g_wh + WOFF_FIN, fb);
}

extern "C" void kernel_launch(void* const* d_in, const int* in_sizes, int n_in,
                              void* d_out, int out_size) {
    (void)in_sizes; (void)n_in; (void)out_size;
    const float* x   = (const float*)d_in[0];
    const float* dw0 = (const float*)d_in[1];
    const float* db0 = (const float*)d_in[2];
    const float* rdw = (const float*)d_in[3];
    const float* rdb = (const float*)d_in[4];
    const float* rpw = (const float*)d_in[5];
    const float* rpb = (const float*)d_in[6];
    const float* cw1 = (const float*)d_in[7];
    const float* cb1 = (const float*)d_in[8];
    const float* cw2 = (const float*)d_in[9];
    const float* cb2 = (const float*)d_in[10];
    const float* fw  = (const float*)d_in[11];
    const float* fb  = (const float*)d_in[12];
    float* out = (float*)d_out;

    cudaFuncSetAttribute(mix9s_kernel,
                         cudaFuncAttributeMaxDynamicSharedMemorySize, SMEM_BYTES);

    prep_kernel<<<296, 1024>>>(rdw, rpw, cw1, cw2, fw);
    mix9s_kernel<<<1024, 512, SMEM_BYTES>>>(
        x, dw0, db0, rdb, rpb, cb1, cb2, fb, out);
}

// round 8
// speedup vs baseline: 4.4210x; 1.6047x over previous
#include <cuda_runtime.h>
#include <cuda_fp16.h>

#define HW 225
#define ZROW 225          // guaranteed-zero row (all 128 channels zero)
#define NROWS 226
#define NCH 128
// two half buffers [226][128]
#define SMEM_BYTES (2*NROWS*NCH*2)

// per-direction tap offsets: d0 horiz, d1 vert, d2 anti-diag, d3 main diag
__constant__ int c_DI0[4] = { 0,-1, 1,-1};
__constant__ int c_DJ0[4] = {-1, 0,-1,-1};
__constant__ int c_DI2[4] = { 0, 1,-1, 1};
__constant__ int c_DJ2[4] = { 1, 0, 1, 1};

// ---- f16 weight arena ----
#define WOFF_DIR 0
#define WOFF_PW  196608
#define WOFF_C1  262144
#define WOFF_C2  278528
#define WOFF_FIN 294912
#define WTOTAL   303104
__device__ __align__(16) __half g_wh[WTOTAL];

__global__ void prep_kernel(const float* __restrict__ rdw,
                            const float* __restrict__ rpw,
                            const float* __restrict__ cw1,
                            const float* __restrict__ cw2,
                            const float* __restrict__ fw) {
    for (int idx = blockIdx.x*blockDim.x + threadIdx.x; idx < WTOTAL;
         idx += gridDim.x*blockDim.x) {
        float v;
        if (idx < WOFF_PW) {
            int c = idx & 127;
            int o = (idx >> 7) & 127;
            int r = idx >> 14;          // i*3 + t
            int t = r % 3;
            int i = r / 3;
            v = rdw[((i*128 + o)*128 + c)*3 + t];
        } else if (idx < WOFF_C1) {
            v = rpw[idx - WOFF_PW];
        } else if (idx < WOFF_C2) {
            v = cw1[idx - WOFF_C1];
        } else if (idx < WOFF_FIN) {
            v = cw2[idx - WOFF_C2];
        } else {
            v = fw[idx - WOFF_FIN];
        }
        g_wh[idx] = __float2half(v);
    }
}

__device__ __forceinline__ float silu_f(float x) {
    return x * (1.0f / (1.0f + __expf(-x)));
}

// half layout [p][c]: row = 256B = 16 granules of 16B (8 halves), granule
// index XOR-swizzled with (p&7).  half index of (p,c):
__device__ __forceinline__ int hidx(int p, int c) {
    return p*128 + ((((c >> 3) ^ (p & 7)) << 3) | (c & 7));
}

__device__ __forceinline__ void mma_16816(float* d,
    unsigned a0, unsigned a1, unsigned a2, unsigned a3,
    unsigned b0, unsigned b1)
{
    asm volatile(
        "mma.sync.aligned.m16n8k16.row.col.f32.f16.f16.f32 "
        "{%0,%1,%2,%3}, {%4,%5,%6,%7}, {%8,%9}, {%0,%1,%2,%3};\n"
        : "+f"(d[0]), "+f"(d[1]), "+f"(d[2]), "+f"(d[3])
        : "r"(a0), "r"(a1), "r"(a2), "r"(a3), "r"(b0), "r"(b1));
}

// MMA layer, Cin=128 -> Co=128, half activations in smem.
// 16 warps = 4 out-groups (32 ch = 2 m-tiles) x 4 pos-cols (64 pos = 8 n-tiles).
// Each B fragment feeds 2 MMAs (both m-tiles).
template<int NTAPS, bool ACT, bool RESID>
__device__ __forceinline__ void layer_mma(
    const __half* __restrict__ sin,
    __half* __restrict__ sout,
    const __half* __restrict__ wh,
    const float* __restrict__ bias,
    const __half* __restrict__ sres,
    int di0, int dj0, int di2, int dj2)
{
    const int tid  = threadIdx.x;
    const int wid  = tid >> 5;
    const int lane = tid & 31;
    const int tg = lane >> 2, tk = lane & 3;
    const int oz = wid >> 2, pc = wid & 3;
    const int ob = oz * 32;
    const int pbase = pc * 64;
    const unsigned* w32 = reinterpret_cast<const unsigned*>(wh);
    const int wb0 = (ob + tg)*64 + tk;
    const char* sb = reinterpret_cast<const char*>(sin);

    float bl[2], bh[2];
#pragma unroll
    for (int mt = 0; mt < 2; mt++) {
        bl[mt] = bias[ob + mt*16 + tg];
        bh[mt] = bias[ob + mt*16 + tg + 8];
    }

    float acc[2][8][4];
#pragma unroll
    for (int mt = 0; mt < 2; mt++)
#pragma unroll
        for (int i = 0; i < 8; i++)
#pragma unroll
            for (int u = 0; u < 4; u++) acc[mt][i][u] = 0.f;

#pragma unroll 1
    for (int tap = 0; tap < NTAPS; tap++) {
        int di = 0, dj = 0;
        if (NTAPS == 3) {
            di = (tap == 0) ? di0 : ((tap == 1) ? 0 : di2);
            dj = (tap == 0) ? dj0 : ((tap == 1) ? 0 : dj2);
        }
        int baseB[8], rx[8];
#pragma unroll
        for (int i = 0; i < 8; i++) {
            int p = pbase + i*8 + tg;
            int r = ZROW;
            if (p < HW) {
                if (NTAPS == 3 && tap != 1) {
                    int pi = p / 15, pj = p - pi*15;
                    if ((unsigned)(pi + di) < 15u && (unsigned)(pj + dj) < 15u)
                        r = p + di*15 + dj;
                } else {
                    r = p;
                }
            }
            baseB[i] = r*256 + 4*tk;
            rx[i] = r & 7;
        }
        const unsigned* wt = w32 + tap*8192;

#pragma unroll 1
        for (int s = 0; s < 8; s++) {
            unsigned a0 = wt[wb0 + 8*s];
            unsigned a1 = wt[wb0 + 512 + 8*s];
            unsigned a2 = wt[wb0 + 8*s + 4];
            unsigned a3 = wt[wb0 + 512 + 8*s + 4];
            unsigned a4 = wt[wb0 + 1024 + 8*s];
            unsigned a5 = wt[wb0 + 1536 + 8*s];
            unsigned a6 = wt[wb0 + 1024 + 8*s + 4];
            unsigned a7 = wt[wb0 + 1536 + 8*s + 4];
#pragma unroll
            for (int i = 0; i < 8; i++) {
                unsigned b0 = *reinterpret_cast<const unsigned*>(
                    sb + baseB[i] + (((2*s) ^ rx[i]) << 4));
                unsigned b1 = *reinterpret_cast<const unsigned*>(
                    sb + baseB[i] + (((2*s + 1) ^ rx[i]) << 4));
                mma_16816(acc[0][i], a0, a1, a2, a3, b0, b1);
                mma_16816(acc[1][i], a4, a5, a6, a7, b0, b1);
            }
        }
    }

    // epilogue
#pragma unroll
    for (int i = 0; i < 8; i++) {
        int p0 = pbase + i*8 + tk*2;
        int p1 = p0 + 1;
#pragma unroll
        for (int mt = 0; mt < 2; mt++) {
            const int o0 = ob + mt*16 + tg, o1 = o0 + 8;
            float v00 = acc[mt][i][0] + bl[mt];
            float v01 = acc[mt][i][1] + bl[mt];
            float v10 = acc[mt][i][2] + bh[mt];
            float v11 = acc[mt][i][3] + bh[mt];
            if (ACT) {
                v00 = silu_f(v00); v01 = silu_f(v01);
                v10 = silu_f(v10); v11 = silu_f(v11);
            }
            if (p0 < HW) {
                int i00 = hidx(p0, o0), i10 = hidx(p0, o1);
                if (RESID) {
                    v00 += __half2float(sres[i00]);
                    v10 += __half2float(sres[i10]);
                }
                sout[i00] = __float2half(v00);
                sout[i10] = __float2half(v10);
            }
            if (p1 < HW) {
                int i01 = hidx(p1, o0), i11 = hidx(p1, o1);
                if (RESID) {
                    v01 += __half2float(sres[i01]);
                    v11 += __half2float(sres[i11]);
                }
                sout[i01] = __float2half(v01);
                sout[i11] = __float2half(v11);
            }
        }
    }
}

// Final 1x1, 128 -> 64, to global fp32.
// 16 warps = 2 out-groups (32 ch) x 8 pos-cols (32 pos = 4 n-tiles).
__device__ __forceinline__ void final_mma(
    const __half* __restrict__ sin,
    float* __restrict__ gout,
    const __half* __restrict__ wh,
    const float* __restrict__ bias)
{
    const int tid  = threadIdx.x;
    const int wid  = tid >> 5;
    const int lane = tid & 31;
    const int tg = lane >> 2, tk = lane & 3;
    const int oz = wid >> 3, pc = wid & 7;
    const int ob = oz * 32;
    const int pbase = pc * 32;
    const unsigned* w32 = reinterpret_cast<const unsigned*>(wh);
    const int wb0 = (ob + tg)*64 + tk;
    const char* sb = reinterpret_cast<const char*>(sin);

    float bl[2], bh[2];
#pragma unroll
    for (int mt = 0; mt < 2; mt++) {
        bl[mt] = bias[ob + mt*16 + tg];
        bh[mt] = bias[ob + mt*16 + tg + 8];
    }

    float acc[2][4][4];
#pragma unroll
    for (int mt = 0; mt < 2; mt++)
#pragma unroll
        for (int i = 0; i < 4; i++)
#pragma unroll
            for (int u = 0; u < 4; u++) acc[mt][i][u] = 0.f;

    int baseB[4], rx[4];
#pragma unroll
    for (int i = 0; i < 4; i++) {
        int p = pbase + i*8 + tg;
        int r = (p < HW) ? p : ZROW;
        baseB[i] = r*256 + 4*tk;
        rx[i] = r & 7;
    }

#pragma unroll 1
    for (int s = 0; s < 8; s++) {
        unsigned a0 = w32[wb0 + 8*s];
        unsigned a1 = w32[wb0 + 512 + 8*s];
        unsigned a2 = w32[wb0 + 8*s + 4];
        unsigned a3 = w32[wb0 + 512 + 8*s + 4];
        unsigned a4 = w32[wb0 + 1024 + 8*s];
        unsigned a5 = w32[wb0 + 1536 + 8*s];
        unsigned a6 = w32[wb0 + 1024 + 8*s + 4];
        unsigned a7 = w32[wb0 + 1536 + 8*s + 4];
#pragma unroll
        for (int i = 0; i < 4; i++) {
            unsigned b0 = *reinterpret_cast<const unsigned*>(
                sb + baseB[i] + (((2*s) ^ rx[i]) << 4));
            unsigned b1 = *reinterpret_cast<const unsigned*>(
                sb + baseB[i] + (((2*s + 1) ^ rx[i]) << 4));
            mma_16816(acc[0][i], a0, a1, a2, a3, b0, b1);
            mma_16816(acc[1][i], a4, a5, a6, a7, b0, b1);
        }
    }

#pragma unroll
    for (int i = 0; i < 4; i++) {
        int p0 = pbase + i*8 + tk*2;
        int p1 = p0 + 1;
#pragma unroll
        for (int mt = 0; mt < 2; mt++) {
            const int o0 = ob + mt*16 + tg, o1 = o0 + 8;
            if (p0 < HW) {
                gout[o0*HW + p0] = acc[mt][i][0] + bl[mt];
                gout[o1*HW + p0] = acc[mt][i][2] + bh[mt];
            }
            if (p1 < HW) {
                gout[o0*HW + p1] = acc[mt][i][1] + bl[mt];
                gout[o1*HW + p1] = acc[mt][i][3] + bh[mt];
            }
        }
    }
}

__global__ void __launch_bounds__(512, 1)
mix9s_kernel(const float* __restrict__ x,
             const float* __restrict__ dw0, const float* __restrict__ db0,
             const float* __restrict__ rdb, const float* __restrict__ rpb,
             const float* __restrict__ cb1, const float* __restrict__ cb2,
             const float* __restrict__ fb,
             float* __restrict__ out)
{
    extern __shared__ __half smem_h[];
    __half* bufA = smem_h;                      // swizzled half [226][128]
    __half* bufB = smem_h + NROWS*NCH;

    const int tid = threadIdx.x;
    const int b = blockIdx.x & 255;
    const int d = blockIdx.x >> 8;
    const int di0 = c_DI0[d], dj0 = c_DJ0[d], di2 = c_DI2[d], dj2 = c_DJ2[d];

    // zero rows
    if (tid < NCH) {
        bufA[ZROW*NCH + tid] = __float2half(0.f);
        bufB[ZROW*NCH + tid] = __float2half(0.f);
    }
    // stage x fp32 into scratch at start of bufB: xs[c][0..225], slot 225 = 0
    float* xs = reinterpret_cast<float*>(bufB);
    const float* xb = x + b*(2*HW);
    for (int idx = tid; idx < 2*HW; idx += 512) {
        int c = idx / HW;
        int p = idx - c*HW;
        xs[c*NROWS + p] = xb[idx];
    }
    if (tid < 2) xs[tid*NROWS + HW] = 0.f;
    __syncthreads();

    // ---- dconv0: Cin=2, 3 taps, silu -> bufA (scalar) ----
    {
        const int oz = tid >> 4, pl = tid & 15;   // 32 groups x 4 outputs
        const int ob = oz * 4;
        float wr_[4][2][3];
#pragma unroll
        for (int u = 0; u < 4; u++)
#pragma unroll
            for (int c = 0; c < 2; c++)
#pragma unroll
                for (int t = 0; t < 3; t++)
                    wr_[u][c][t] = dw0[((ob+u)*2 + c)*3 + t];
        float bb[4];
#pragma unroll
        for (int u = 0; u < 4; u++) bb[u] = db0[ob+u];

        const int d0 = di0*15 + dj0;
        const int d2 = di2*15 + dj2;
#pragma unroll 1
        for (int ch = 0; ch < 4; ch++) {
#pragma unroll
            for (int j = 0; j < 4; j++) {
                int p = pl + 16*(ch*4 + j);
                bool v = p < HW;
                int rv = v ? p : HW;
                int r0 = HW, r2 = HW;
                int pi = p / 15, pj = p - pi*15;
                if (v && (unsigned)(pi+di0) < 15u && (unsigned)(pj+dj0) < 15u)
                    r0 = p + d0;
                if (v && (unsigned)(pi+di2) < 15u && (unsigned)(pj+dj2) < 15u)
                    r2 = p + d2;

                float v0[2], vc[2], v2[2];
#pragma unroll
                for (int c = 0; c < 2; c++) {
                    v0[c] = xs[c*NROWS + r0];
                    vc[c] = xs[c*NROWS + rv];
                    v2[c] = xs[c*NROWS + r2];
                }
                if (v) {
#pragma unroll
                    for (int u = 0; u < 4; u++) {
                        float a = bb[u];
#pragma unroll
                        for (int c = 0; c < 2; c++) {
                            a = fmaf(wr_[u][c][0], v0[c], a);
                            a = fmaf(wr_[u][c][1], vc[c], a);
                            a = fmaf(wr_[u][c][2], v2[c], a);
                        }
                        bufA[hidx(rv, ob+u)] = __float2half(silu_f(a));
                    }
                }
            }
        }
    }
    __syncthreads();

    // ---- 4 directional res blocks ----
#pragma unroll 1
    for (int i = 0; i < 4; i++) {
        layer_mma<3, true, false>(bufA, bufB,
            g_wh + WOFF_DIR + i*3*16384, rdb + i*128, nullptr,
            di0, dj0, di2, dj2);
        __syncthreads();
        layer_mma<1, true, true>(bufB, bufA,
            g_wh + WOFF_PW + i*16384, rpb + i*128, bufA, 0, 0, 0, 0);
        __syncthreads();
    }

    // ---- Conv0d res block ----
    layer_mma<1, true, false>(bufA, bufB, g_wh + WOFF_C1, cb1, nullptr, 0,0,0,0);
    __syncthreads();
    layer_mma<1, true, true>(bufB, bufA, g_wh + WOFF_C2, cb2, bufA, 0,0,0,0);
    __syncthreads();

    // ---- final 1x1 (128 -> 64) straight to global ----
    final_mma(bufA, out + (b*4 + d)*64*HW, g_wh + WOFF_FIN, fb);
}

extern "C" void kernel_launch(void* const* d_in, const int* in_sizes, int n_in,
                              void* d_out, int out_size) {
    (void)in_sizes; (void)n_in; (void)out_size;
    const float* x   = (const float*)d_in[0];
    const float* dw0 = (const float*)d_in[1];
    const float* db0 = (const float*)d_in[2];
    const float* rdw = (const float*)d_in[3];
    const float* rdb = (const float*)d_in[4];
    const float* rpw = (const float*)d_in[5];
    const float* rpb = (const float*)d_in[6];
    const float* cw1 = (const float*)d_in[7];
    const float* cb1 = (const float*)d_in[8];
    const float* cw2 = (const float*)d_in[9];
    const float* cb2 = (const float*)d_in[10];
    const float* fw  = (const float*)d_in[11];
    const float* fb  = (const float*)d_in[12];
    float* out = (float*)d_out;

    cudaFuncSetAttribute(mix9s_kernel,
                         cudaFuncAttributeMaxDynamicSharedMemorySize, SMEM_BYTES);

    prep_kernel<<<296, 1024>>>(rdw, rpw, cw1, cw2, fw);
    mix9s_kernel<<<1024, 512, SMEM_BYTES>>>(
        x, dw0, db0, rdb, rpb, cb1, cb2, fb, out);
}

// round 9
// speedup vs baseline: 4.4476x; 1.0060x over previous
#include <cuda_runtime.h>
#include <cuda_fp16.h>

#define HW 225
#define ZROW 225          // guaranteed-zero row (all 128 channels zero)
#define NROWS 226
#define NCH 128
// two half buffers [226][128]
#define SMEM_BYTES (2*NROWS*NCH*2)

// per-direction tap offsets: d0 horiz, d1 vert, d2 anti-diag, d3 main diag
__constant__ int c_DI0[4] = { 0,-1, 1,-1};
__constant__ int c_DJ0[4] = {-1, 0,-1,-1};
__constant__ int c_DI2[4] = { 0, 1,-1, 1};
__constant__ int c_DJ2[4] = { 1, 0, 1, 1};

// ---- f16 weight arena ----
#define WOFF_DIR 0
#define WOFF_PW  196608
#define WOFF_C1  262144
#define WOFF_C2  278528
#define WOFF_FIN 294912
#define WTOTAL   303104
__device__ __align__(16) __half g_wh[WTOTAL];

__global__ void prep_kernel(const float* __restrict__ rdw,
                            const float* __restrict__ rpw,
                            const float* __restrict__ cw1,
                            const float* __restrict__ cw2,
                            const float* __restrict__ fw) {
    for (int idx = blockIdx.x*blockDim.x + threadIdx.x; idx < WTOTAL;
         idx += gridDim.x*blockDim.x) {
        float v;
        if (idx < WOFF_PW) {
            int c = idx & 127;
            int o = (idx >> 7) & 127;
            int r = idx >> 14;          // i*3 + t
            int t = r % 3;
            int i = r / 3;
            v = rdw[((i*128 + o)*128 + c)*3 + t];
        } else if (idx < WOFF_C1) {
            v = rpw[idx - WOFF_PW];
        } else if (idx < WOFF_C2) {
            v = cw1[idx - WOFF_C1];
        } else if (idx < WOFF_FIN) {
            v = cw2[idx - WOFF_C2];
        } else {
            v = fw[idx - WOFF_FIN];
        }
        g_wh[idx] = __float2half(v);
    }
}

__device__ __forceinline__ float silu_f(float x) {
    return x * (1.0f / (1.0f + __expf(-x)));
}

// half layout [p][c]: row = 256B = 16 granules of 16B (8 halves), granule
// index XOR-swizzled with (p&7).  half index of (p,c):
__device__ __forceinline__ int hidx(int p, int c) {
    return p*128 + ((((c >> 3) ^ (p & 7)) << 3) | (c & 7));
}

__device__ __forceinline__ void mma_16816(float* d,
    unsigned a0, unsigned a1, unsigned a2, unsigned a3,
    unsigned b0, unsigned b1)
{
    asm volatile(
        "mma.sync.aligned.m16n8k16.row.col.f32.f16.f16.f32 "
        "{%0,%1,%2,%3}, {%4,%5,%6,%7}, {%8,%9}, {%0,%1,%2,%3};\n"
        : "+f"(d[0]), "+f"(d[1]), "+f"(d[2]), "+f"(d[3])
        : "r"(a0), "r"(a1), "r"(a2), "r"(a3), "r"(b0), "r"(b1));
}

__device__ __forceinline__ void ldsm_x4(unsigned& r0, unsigned& r1,
                                        unsigned& r2, unsigned& r3,
                                        unsigned addr)
{
    asm volatile(
        "ldmatrix.sync.aligned.m8n8.x4.shared.b16 {%0,%1,%2,%3}, [%4];\n"
        : "=r"(r0), "=r"(r1), "=r"(r2), "=r"(r3) : "r"(addr));
}

// MMA layer, Cin=128 -> Co=128, half activations in smem.
// 16 warps = 4 out-groups (32 ch = 2 m-tiles) x 4 pos-cols (64 pos = 8 n-tiles).
// B fragments via ldmatrix.x4: one instruction feeds 4 MMAs (2 k-steps x 2 m).
template<int NTAPS, bool ACT, bool RESID>
__device__ __forceinline__ void layer_mma(
    const __half* __restrict__ sin,
    __half* __restrict__ sout,
    const __half* __restrict__ wh,
    const float* __restrict__ bias,
    const __half* __restrict__ sres,
    int di0, int dj0, int di2, int dj2)
{
    const int tid  = threadIdx.x;
    const int wid  = tid >> 5;
    const int lane = tid & 31;
    const int tg = lane >> 2, tk = lane & 3;
    const int lr = lane & 7;        // row-within-tile for ldmatrix
    const int lq = lane >> 3;       // k-granule slot 0..3
    const int oz = wid >> 2, pc = wid & 3;
    const int ob = oz * 32;
    const int pbase = pc * 64;
    const unsigned* w32 = reinterpret_cast<const unsigned*>(wh);
    const int wb0 = (ob + tg)*64 + tk;
    const unsigned sbase = (unsigned)__cvta_generic_to_shared(sin);

    float bl[2], bh[2];
#pragma unroll
    for (int mt = 0; mt < 2; mt++) {
        bl[mt] = bias[ob + mt*16 + tg];
        bh[mt] = bias[ob + mt*16 + tg + 8];
    }

    float acc[2][8][4];
#pragma unroll
    for (int mt = 0; mt < 2; mt++)
#pragma unroll
        for (int i = 0; i < 8; i++)
#pragma unroll
            for (int u = 0; u < 4; u++) acc[mt][i][u] = 0.f;

#pragma unroll 1
    for (int tap = 0; tap < NTAPS; tap++) {
        int di = 0, dj = 0;
        if (NTAPS == 3) {
            di = (tap == 0) ? di0 : ((tap == 1) ? 0 : di2);
            dj = (tap == 0) ? dj0 : ((tap == 1) ? 0 : dj2);
        }
        // per-lane ldmatrix row base for each n-tile
        unsigned abase[8]; int rx[8];
#pragma unroll
        for (int i = 0; i < 8; i++) {
            int p = pbase + i*8 + lr;
            int r = ZROW;
            if (p < HW) {
                if (NTAPS == 3 && tap != 1) {
                    int pi = p / 15, pj = p - pi*15;
                    if ((unsigned)(pi + di) < 15u && (unsigned)(pj + dj) < 15u)
                        r = p + di*15 + dj;
                } else {
                    r = p;
                }
            }
            abase[i] = sbase + r*256;
            rx[i] = r & 7;
        }
        const unsigned* wt = w32 + tap*8192;

#pragma unroll 1
        for (int sp = 0; sp < 4; sp++) {
            // A fragments for s = 2sp, 2sp+1, both m-tiles (uniform LDG)
            unsigned aA[2][8];
#pragma unroll
            for (int s2 = 0; s2 < 2; s2++) {
                int s = 2*sp + s2;
                aA[s2][0] = wt[wb0 + 8*s];
                aA[s2][1] = wt[wb0 + 512 + 8*s];
                aA[s2][2] = wt[wb0 + 8*s + 4];
                aA[s2][3] = wt[wb0 + 512 + 8*s + 4];
                aA[s2][4] = wt[wb0 + 1024 + 8*s];
                aA[s2][5] = wt[wb0 + 1536 + 8*s];
                aA[s2][6] = wt[wb0 + 1024 + 8*s + 4];
                aA[s2][7] = wt[wb0 + 1536 + 8*s + 4];
            }
            const int gq = 4*sp + lq;
#pragma unroll
            for (int i = 0; i < 8; i++) {
                unsigned b0, b1, b2, b3;
                ldsm_x4(b0, b1, b2, b3, abase[i] + ((gq ^ rx[i]) << 4));
                mma_16816(acc[0][i], aA[0][0], aA[0][1], aA[0][2], aA[0][3], b0, b1);
                mma_16816(acc[1][i], aA[0][4], aA[0][5], aA[0][6], aA[0][7], b0, b1);
                mma_16816(acc[0][i], aA[1][0], aA[1][1], aA[1][2], aA[1][3], b2, b3);
                mma_16816(acc[1][i], aA[1][4], aA[1][5], aA[1][6], aA[1][7], b2, b3);
            }
        }
    }

    // epilogue
#pragma unroll
    for (int i = 0; i < 8; i++) {
        int p0 = pbase + i*8 + tk*2;
        int p1 = p0 + 1;
#pragma unroll
        for (int mt = 0; mt < 2; mt++) {
            const int o0 = ob + mt*16 + tg, o1 = o0 + 8;
            float v00 = acc[mt][i][0] + bl[mt];
            float v01 = acc[mt][i][1] + bl[mt];
            float v10 = acc[mt][i][2] + bh[mt];
            float v11 = acc[mt][i][3] + bh[mt];
            if (ACT) {
                v00 = silu_f(v00); v01 = silu_f(v01);
                v10 = silu_f(v10); v11 = silu_f(v11);
            }
            if (p0 < HW) {
                int i00 = hidx(p0, o0), i10 = hidx(p0, o1);
                if (RESID) {
                    v00 += __half2float(sres[i00]);
                    v10 += __half2float(sres[i10]);
                }
                sout[i00] = __float2half(v00);
                sout[i10] = __float2half(v10);
            }
            if (p1 < HW) {
                int i01 = hidx(p1, o0), i11 = hidx(p1, o1);
                if (RESID) {
                    v01 += __half2float(sres[i01]);
                    v11 += __half2float(sres[i11]);
                }
                sout[i01] = __float2half(v01);
                sout[i11] = __float2half(v11);
            }
        }
    }
}

// Final 1x1, 128 -> 64, to global fp32.
// 16 warps = 2 out-groups (32 ch) x 8 pos-cols (32 pos = 4 n-tiles).
__device__ __forceinline__ void final_mma(
    const __half* __restrict__ sin,
    float* __restrict__ gout,
    const __half* __restrict__ wh,
    const float* __restrict__ bias)
{
    const int tid  = threadIdx.x;
    const int wid  = tid >> 5;
    const int lane = tid & 31;
    const int tg = lane >> 2, tk = lane & 3;
    const int lr = lane & 7;
    const int lq = lane >> 3;
    const int oz = wid >> 3, pc = wid & 7;
    const int ob = oz * 32;
    const int pbase = pc * 32;
    const unsigned* w32 = reinterpret_cast<const unsigned*>(wh);
    const int wb0 = (ob + tg)*64 + tk;
    const unsigned sbase = (unsigned)__cvta_generic_to_shared(sin);

    float bl[2], bh[2];
#pragma unroll
    for (int mt = 0; mt < 2; mt++) {
        bl[mt] = bias[ob + mt*16 + tg];
        bh[mt] = bias[ob + mt*16 + tg + 8];
    }

    float acc[2][4][4];
#pragma unroll
    for (int mt = 0; mt < 2; mt++)
#pragma unroll
        for (int i = 0; i < 4; i++)
#pragma unroll
            for (int u = 0; u < 4; u++) acc[mt][i][u] = 0.f;

    unsigned abase[4]; int rx[4];
#pragma unroll
    for (int i = 0; i < 4; i++) {
        int p = pbase + i*8 + lr;
        int r = (p < HW) ? p : ZROW;
        abase[i] = sbase + r*256;
        rx[i] = r & 7;
    }

#pragma unroll 1
    for (int sp = 0; sp < 4; sp++) {
        unsigned aA[2][8];
#pragma unroll
        for (int s2 = 0; s2 < 2; s2++) {
            int s = 2*sp + s2;
            aA[s2][0] = w32[wb0 + 8*s];
            aA[s2][1] = w32[wb0 + 512 + 8*s];
            aA[s2][2] = w32[wb0 + 8*s + 4];
            aA[s2][3] = w32[wb0 + 512 + 8*s + 4];
            aA[s2][4] = w32[wb0 + 1024 + 8*s];
            aA[s2][5] = w32[wb0 + 1536 + 8*s];
            aA[s2][6] = w32[wb0 + 1024 + 8*s + 4];
            aA[s2][7] = w32[wb0 + 1536 + 8*s + 4];
        }
        const int gq = 4*sp + lq;
#pragma unroll
        for (int i = 0; i < 4; i++) {
            unsigned b0, b1, b2, b3;
            ldsm_x4(b0, b1, b2, b3, abase[i] + ((gq ^ rx[i]) << 4));
            mma_16816(acc[0][i], aA[0][0], aA[0][1], aA[0][2], aA[0][3], b0, b1);
            mma_16816(acc[1][i], aA[0][4], aA[0][5], aA[0][6], aA[0][7], b0, b1);
            mma_16816(acc[0][i], aA[1][0], aA[1][1], aA[1][2], aA[1][3], b2, b3);
            mma_16816(acc[1][i], aA[1][4], aA[1][5], aA[1][6], aA[1][7], b2, b3);
        }
    }

#pragma unroll
    for (int i = 0; i < 4; i++) {
        int p0 = pbase + i*8 + tk*2;
        int p1 = p0 + 1;
#pragma unroll
        for (int mt = 0; mt < 2; mt++) {
            const int o0 = ob + mt*16 + tg, o1 = o0 + 8;
            if (p0 < HW) {
                gout[o0*HW + p0] = acc[mt][i][0] + bl[mt];
                gout[o1*HW + p0] = acc[mt][i][2] + bh[mt];
            }
            if (p1 < HW) {
                gout[o0*HW + p1] = acc[mt][i][1] + bl[mt];
                gout[o1*HW + p1] = acc[mt][i][3] + bh[mt];
            }
        }
    }
}

__global__ void __launch_bounds__(512, 1)
mix9s_kernel(const float* __restrict__ x,
             const float* __restrict__ dw0, const float* __restrict__ db0,
             const float* __restrict__ rdb, const float* __restrict__ rpb,
             const float* __restrict__ cb1, const float* __restrict__ cb2,
             const float* __restrict__ fb,
             float* __restrict__ out)
{
    extern __shared__ __half smem_h[];
    __half* bufA = smem_h;                      // swizzled half [226][128]
    __half* bufB = smem_h + NROWS*NCH;

    const int tid = threadIdx.x;
    const int b = blockIdx.x & 255;
    const int d = blockIdx.x >> 8;
    const int di0 = c_DI0[d], dj0 = c_DJ0[d], di2 = c_DI2[d], dj2 = c_DJ2[d];

    // zero rows
    if (tid < NCH) {
        bufA[ZROW*NCH + tid] = __float2half(0.f);
        bufB[ZROW*NCH + tid] = __float2half(0.f);
    }
    // stage x fp32 into scratch at start of bufB: xs[c][0..225], slot 225 = 0
    float* xs = reinterpret_cast<float*>(bufB);
    const float* xb = x + b*(2*HW);
    for (int idx = tid; idx < 2*HW; idx += 512) {
        int c = idx / HW;
        int p = idx - c*HW;
        xs[c*NROWS + p] = xb[idx];
    }
    if (tid < 2) xs[tid*NROWS + HW] = 0.f;
    __syncthreads();

    // ---- dconv0: Cin=2, 3 taps, silu -> bufA (scalar) ----
    {
        const int oz = tid >> 4, pl = tid & 15;   // 32 groups x 4 outputs
        const int ob = oz * 4;
        float wr_[4][2][3];
#pragma unroll
        for (int u = 0; u < 4; u++)
#pragma unroll
            for (int c = 0; c < 2; c++)
#pragma unroll
                for (int t = 0; t < 3; t++)
                    wr_[u][c][t] = dw0[((ob+u)*2 + c)*3 + t];
        float bb[4];
#pragma unroll
        for (int u = 0; u < 4; u++) bb[u] = db0[ob+u];

        const int d0 = di0*15 + dj0;
        const int d2 = di2*15 + dj2;
#pragma unroll 1
        for (int ch = 0; ch < 4; ch++) {
#pragma unroll
            for (int j = 0; j < 4; j++) {
                int p = pl + 16*(ch*4 + j);
                bool v = p < HW;
                int rv = v ? p : HW;
                int r0 = HW, r2 = HW;
                int pi = p / 15, pj = p - pi*15;
                if (v && (unsigned)(pi+di0) < 15u && (unsigned)(pj+dj0) < 15u)
                    r0 = p + d0;
                if (v && (unsigned)(pi+di2) < 15u && (unsigned)(pj+dj2) < 15u)
                    r2 = p + d2;

                float v0[2], vc[2], v2[2];
#pragma unroll
                for (int c = 0; c < 2; c++) {
                    v0[c] = xs[c*NROWS + r0];
                    vc[c] = xs[c*NROWS + rv];
                    v2[c] = xs[c*NROWS + r2];
                }
                if (v) {
#pragma unroll
                    for (int u = 0; u < 4; u++) {
                        float a = bb[u];
#pragma unroll
                        for (int c = 0; c < 2; c++) {
                            a = fmaf(wr_[u][c][0], v0[c], a);
                            a = fmaf(wr_[u][c][1], vc[c], a);
                            a = fmaf(wr_[u][c][2], v2[c], a);
                        }
                        bufA[hidx(rv, ob+u)] = __float2half(silu_f(a));
                    }
                }
            }
        }
    }
    __syncthreads();

    // ---- 4 directional res blocks ----
#pragma unroll 1
    for (int i = 0; i < 4; i++) {
        layer_mma<3, true, false>(bufA, bufB,
            g_wh + WOFF_DIR + i*3*16384, rdb + i*128, nullptr,
            di0, dj0, di2, dj2);
        __syncthreads();
        layer_mma<1, true, true>(bufB, bufA,
            g_wh + WOFF_PW + i*16384, rpb + i*128, bufA, 0, 0, 0, 0);
        __syncthreads();
    }

    // ---- Conv0d res block ----
    layer_mma<1, true, false>(bufA, bufB, g_wh + WOFF_C1, cb1, nullptr, 0,0,0,0);
    __syncthreads();
    layer_mma<1, true, true>(bufB, bufA, g_wh + WOFF_C2, cb2, bufA, 0,0,0,0);
    __syncthreads();

    // ---- final 1x1 (128 -> 64) straight to global ----
    final_mma(bufA, out + (b*4 + d)*64*HW, g_wh + WOFF_FIN, fb);
}

extern "C" void kernel_launch(void* const* d_in, const int* in_sizes, int n_in,
                              void* d_out, int out_size) {
    (void)in_sizes; (void)n_in; (void)out_size;
    const float* x   = (const float*)d_in[0];
    const float* dw0 = (const float*)d_in[1];
    const float* db0 = (const float*)d_in[2];
    const float* rdw = (const float*)d_in[3];
    const float* rdb = (const float*)d_in[4];
    const float* rpw = (const float*)d_in[5];
    const float* rpb = (const float*)d_in[6];
    const float* cw1 = (const float*)d_in[7];
    const float* cb1 = (const float*)d_in[8];
    const float* cw2 = (const float*)d_in[9];
    const float* cb2 = (const float*)d_in[10];
    const float* fw  = (const float*)d_in[11];
    const float* fb  = (const float*)d_in[12];
    float* out = (float*)d_out;

    cudaFuncSetAttribute(mix9s_kernel,
                         cudaFuncAttributeMaxDynamicSharedMemorySize, SMEM_BYTES);

    prep_kernel<<<296, 1024>>>(rdw, rpw, cw1, cw2, fw);
    mix9s_kernel<<<1024, 512, SMEM_BYTES>>>(
        x, dw0, db0, rdb, rpb, cb1, cb2, fb, out);
}